// round 10
// baseline (speedup 1.0000x reference)
#include <cuda_runtime.h>
#include <cuda_bf16.h>
#include <math.h>
#include <stdint.h>

#define Nn 64
#define Tt 32
#define DA 1280
#define PP 16
#define HH 512
#define H4 2048
#define WD 300
#define VV 32000

// ---------------- device scratch (no allocs allowed) ----------------
__device__ float g_cwT[DA * HH];            // conv_w transposed [c][h]
__device__ float g_Aproj[Nn * PP * HH];     // [n*16+p][512]
__device__ float g_h[2][Nn * HH];           // double-buffered h
__device__ float g_c[Nn * HH];
__device__ float g_w[Nn * PP];              // attention weights for current step
__device__ float g_xa[Tt * Nn * H4];        // x@Wx + b, row r = t*64+n
__device__ float g_AW[Nn * PP * H4];        // Aproj@Wattn, [n*16+p][2048]

// bf16-split operands for the HMMA vocab GEMM (K-major)
__device__ __align__(16) __nv_bfloat16 g_Ah[Nn * Tt * HH];   // [2048][512], row n*32+t
__device__ __align__(16) __nv_bfloat16 g_Al[Nn * Tt * HH];
__device__ __align__(16) __nv_bfloat16 g_BhT[(size_t)VV * HH];   // [32000][512]
__device__ __align__(16) __nv_bfloat16 g_BlT[(size_t)VV * HH];

// persistent-kernel sync state
__device__ unsigned int g_bar_count;   // zero-init, returns to 0 every barrier
__device__ unsigned int g_bar_gen;     // monotonic (read-before-arrive, wrap-safe)
__device__ unsigned int g_wcnt;        // attw producer flag (reset at kernel start)

// ---------------- portable PTX helpers (sm_80+ features only) ----------------
__device__ __forceinline__ uint32_t smem_u32(const void* p) {
    uint32_t a;
    asm("{ .reg .u64 t; cvta.to.shared.u64 t, %1; cvt.u32.u64 %0, t; }" : "=r"(a) : "l"(p));
    return a;
}
__device__ __forceinline__ void cpasync16(uint32_t dst, const void* src) {
    asm volatile("cp.async.cg.shared.global [%0], [%1], 16;" :: "r"(dst), "l"(src) : "memory");
}
__device__ __forceinline__ void cp_commit() {
    asm volatile("cp.async.commit_group;" ::: "memory");
}
__device__ __forceinline__ void ldmx4(uint32_t* r, uint32_t addr) {
    asm volatile("ldmatrix.sync.aligned.m8n8.x4.shared.b16 {%0,%1,%2,%3}, [%4];"
                 : "=r"(r[0]), "=r"(r[1]), "=r"(r[2]), "=r"(r[3]) : "r"(addr));
}
__device__ __forceinline__ void mma16816(float* d, const uint32_t* a, uint32_t b0, uint32_t b1) {
    asm volatile(
        "mma.sync.aligned.m16n8k16.row.col.f32.bf16.bf16.f32 "
        "{%0,%1,%2,%3}, {%4,%5,%6,%7}, {%8,%9}, {%0,%1,%2,%3};"
        : "+f"(d[0]), "+f"(d[1]), "+f"(d[2]), "+f"(d[3])
        : "r"(a[0]), "r"(a[1]), "r"(a[2]), "r"(a[3]), "r"(b0), "r"(b1));
}

// Global barrier for 128 co-resident blocks. Read gen BEFORE arriving (atomic),
// so a racing completion can't strand us; fences order data around the barrier.
__device__ __forceinline__ void grid_barrier128() {
    __syncthreads();
    if (threadIdx.x == 0) {
        __threadfence();
        unsigned int gen = atomicAdd(&g_bar_gen, 0u);
        unsigned int t = atomicAdd(&g_bar_count, 1u);
        if (t == 127u) {
            g_bar_count = 0u;
            __threadfence();
            atomicAdd(&g_bar_gen, 1u);
        } else {
            while (atomicAdd(&g_bar_gen, 0u) == gen) { __nanosleep(64); }
        }
        __threadfence();
    }
    __syncthreads();
}

// ---------------- K0: transpose conv_w [512][1280] -> g_cwT [1280][512] ----------------
__global__ void k_transpose(const float* __restrict__ w) {
    __shared__ float tile[32][33];
    int c0 = blockIdx.x * 32, h0 = blockIdx.y * 32;
    for (int i = threadIdx.y; i < 32; i += 8)
        tile[i][threadIdx.x] = w[(h0 + i) * DA + c0 + threadIdx.x];
    __syncthreads();
    for (int i = threadIdx.y; i < 32; i += 8)
        g_cwT[(c0 + i) * HH + h0 + threadIdx.x] = tile[threadIdx.x][i];
}

// ---------------- K1: Aproj + fused h0/c0 ----------------
__global__ void k_conv(const float* __restrict__ A, const float* __restrict__ cb) {
    int n = blockIdx.x >> 2, cg = blockIdx.x & 3;
    int j = cg * 128 + threadIdx.x;
    __shared__ float a_sm[256 * 16];
    float acc[16];
#pragma unroll
    for (int p = 0; p < 16; p++) acc[p] = 0.f;
    for (int k0 = 0; k0 < DA; k0 += 256) {
        __syncthreads();
        const float* src = A + ((size_t)n * DA + k0) * 16;
        for (int idx = threadIdx.x; idx < 256 * 16; idx += 128) a_sm[idx] = src[idx];
        __syncthreads();
#pragma unroll 4
        for (int kk = 0; kk < 256; kk++) {
            float w = g_cwT[(k0 + kk) * HH + j];
            const float4* ar = (const float4*)&a_sm[kk * 16];
            float4 a0 = ar[0], a1 = ar[1], a2 = ar[2], a3 = ar[3];
            acc[0]  += a0.x * w; acc[1]  += a0.y * w; acc[2]  += a0.z * w; acc[3]  += a0.w * w;
            acc[4]  += a1.x * w; acc[5]  += a1.y * w; acc[6]  += a1.z * w; acc[7]  += a1.w * w;
            acc[8]  += a2.x * w; acc[9]  += a2.y * w; acc[10] += a2.z * w; acc[11] += a2.w * w;
            acc[12] += a3.x * w; acc[13] += a3.y * w; acc[14] += a3.z * w; acc[15] += a3.w * w;
        }
    }
    float bb = cb[j];
    float s = 0.f;
#pragma unroll
    for (int p = 0; p < 16; p++) {
        g_Aproj[(n * 16 + p) * HH + j] = acc[p] + bb;
        s += acc[p];
    }
    s = s * (1.f / 16.f) + bb;          // mean_p(acc[p] + bb)
    g_h[0][n * HH + j] = s;
    g_c[n * HH + j] = s;
}

// ---------------- K2: xa[r][j] = emb(cap)[r] @ Wx + b, r = t*64+n ----------------
__global__ void k_xa(const int* __restrict__ caps, const float* __restrict__ We,
                     const float* __restrict__ Wx, const float* __restrict__ bias) {
    int col = blockIdx.x * 128 + threadIdx.x;
    int r0 = blockIdx.y * 32;
    __shared__ int tok[32];
    __shared__ float x_sm[32 * 304];
    if (threadIdx.x < 32) {
        int rr = r0 + threadIdx.x;
        int n = rr & 63, t = rr >> 6;
        tok[threadIdx.x] = caps[n * Tt + t];
    }
    __syncthreads();
    for (int idx = threadIdx.x; idx < 32 * 300; idx += 128) {
        int r = idx / 300, c = idx - r * 300;
        x_sm[r * 304 + c] = We[(size_t)tok[r] * 300 + c];
    }
    __syncthreads();
    float acc[32];
#pragma unroll
    for (int r = 0; r < 32; r++) acc[r] = 0.f;
    float w0 = Wx[col], w1 = Wx[H4 + col], w2 = Wx[2 * H4 + col], w3 = Wx[3 * H4 + col];
    for (int k0 = 0; k0 < 300; k0 += 4) {
        float n0 = 0.f, n1 = 0.f, n2 = 0.f, n3 = 0.f;
        if (k0 + 4 < 300) {
            const float* wp = Wx + (size_t)(k0 + 4) * H4 + col;
            n0 = wp[0]; n1 = wp[H4]; n2 = wp[2 * H4]; n3 = wp[3 * H4];
        }
#pragma unroll
        for (int r = 0; r < 32; r++) {
            float4 xv = *(const float4*)&x_sm[r * 304 + k0];
            acc[r] += xv.x * w0 + xv.y * w1 + xv.z * w2 + xv.w * w3;
        }
        w0 = n0; w1 = n1; w2 = n2; w3 = n3;
    }
    float bb = bias[col];
#pragma unroll
    for (int r = 0; r < 32; r++) g_xa[(size_t)(r0 + r) * H4 + col] = acc[r] + bb;
}

// ---------------- K3: AW[r][j] = Aproj[r][:] @ Wattn, r = n*16+p ----------------
__global__ void k_aw(const float* __restrict__ Wattn) {
    int col = blockIdx.x * 128 + threadIdx.x;
    int r0 = blockIdx.y * 32;
    __shared__ float a_sm[32 * 256];
    float acc[32];
#pragma unroll
    for (int r = 0; r < 32; r++) acc[r] = 0.f;
    for (int k0 = 0; k0 < HH; k0 += 256) {
        __syncthreads();
        for (int idx = threadIdx.x; idx < 32 * 256; idx += 128) {
            int r = idx >> 8, c = idx & 255;
            a_sm[idx] = g_Aproj[(r0 + r) * HH + k0 + c];
        }
        __syncthreads();
        for (int kk = 0; kk < 256; kk += 4) {
            float w0 = Wattn[(k0 + kk + 0) * H4 + col];
            float w1 = Wattn[(k0 + kk + 1) * H4 + col];
            float w2 = Wattn[(k0 + kk + 2) * H4 + col];
            float w3 = Wattn[(k0 + kk + 3) * H4 + col];
#pragma unroll
            for (int r = 0; r < 32; r++) {
                float4 av = *(const float4*)&a_sm[r * 256 + kk];
                acc[r] += av.x * w0 + av.y * w1 + av.z * w2 + av.w * w3;
            }
        }
    }
#pragma unroll
    for (int r = 0; r < 32; r++) g_AW[(size_t)(r0 + r) * H4 + col] = acc[r];
}

// ---------------- K4: persistent LSTM chain (all 32 steps, one launch) ----------------
// grid 128 = 32 hc-groups x 4 n-groups; all blocks co-resident (128 <= 148 SMs).
// Per step: hc==0 blocks compute attention weights (flag g_wcnt); everyone runs the
// h@Wh mainloop concurrently, waits on the flag only before the AW combine; one
// global barrier per step. Cross-step global reads use __ldcg (stale-L1 bypass).
__global__ __launch_bounds__(256, 1) void k_steps(const float* __restrict__ Wh) {
    int bx = blockIdx.x;
    int hc = bx & 31, ng = bx >> 5;
    int hc0 = hc * 16, n0 = ng * 16;
    int tid = threadIdx.x;
    __shared__ float h_sm[16][512];
    __shared__ float red_sm[3][16][64];
    __shared__ float w_sm[16][16];

    if (bx == 0 && tid == 0) g_wcnt = 0u;
    grid_barrier128();

    for (int t = 0; t < Tt; t++) {
        int rb = t & 1, wb = rb ^ 1;
        for (int idx = tid; idx < 16 * 512; idx += 256) {
            int r = idx >> 9, k = idx & 511;
            h_sm[r][k] = __ldcg(&g_h[rb][(n0 + r) * HH + k]);
        }
        __syncthreads();

        // ---- attention-weight producers (4 blocks: hc == 0) ----
        if (hc == 0) {
            int n_l = tid >> 4, p = tid & 15;
            const float4* ap = (const float4*)(g_Aproj + (size_t)((n0 + n_l) * 16 + p) * HH);
            const float4* hp = (const float4*)h_sm[n_l];
            float s = 0.f;
#pragma unroll 8
            for (int i = 0; i < 128; i++) {
                float4 a = ap[i], h = hp[i];
                s += a.x * h.x + a.y * h.y + a.z * h.z + a.w * h.w;
            }
            s *= 0.04419417382415922f;   // 1/sqrt(512)
            float m = s;
            for (int off = 8; off; off >>= 1)
                m = fmaxf(m, __shfl_xor_sync(0xffffffffu, m, off, 16));
            float e = expf(s - m);
            float sum = e;
            for (int off = 8; off; off >>= 1)
                sum += __shfl_xor_sync(0xffffffffu, sum, off, 16);
            g_w[(n0 + n_l) * 16 + p] = e / sum;
            __syncthreads();
            if (tid == 0) { __threadfence(); atomicAdd(&g_wcnt, 1u); }
        }

        // ---- h @ Wh mainloop (no dependency on w) ----
        int c = tid & 63, ks = tid >> 6;
        int gate = c >> 4, hcl = c & 15;
        int j = gate * HH + hc0 + hcl;
        const float* whcol = Wh + j;
        float acc[16];
#pragma unroll
        for (int r = 0; r < 16; r++) acc[r] = 0.f;
        int kbeg = ks * 128;
        for (int k = kbeg; k < kbeg + 128; k += 4) {
            float w0 = whcol[(k + 0) * H4];
            float w1 = whcol[(k + 1) * H4];
            float w2 = whcol[(k + 2) * H4];
            float w3 = whcol[(k + 3) * H4];
#pragma unroll
            for (int r = 0; r < 16; r++) {
                float4 h4 = *(const float4*)&h_sm[r][k];
                acc[r] += h4.x * w0 + h4.y * w1 + h4.z * w2 + h4.w * w3;
            }
        }

        // ---- wait for this step's attention weights, then combine ----
        if (tid == 0) {
            while (atomicAdd(&g_wcnt, 0u) < 4u * (unsigned)(t + 1)) { }
            __threadfence();
        }
        __syncthreads();
        w_sm[tid >> 4][tid & 15] = __ldcg(&g_w[(n0 + (tid >> 4)) * 16 + (tid & 15)]);
        __syncthreads();

#pragma unroll
        for (int pp = 0; pp < 4; pp++) {
            int p = ks * 4 + pp;
#pragma unroll
            for (int r = 0; r < 16; r++)
                acc[r] += w_sm[r][p] * g_AW[((size_t)(n0 + r) * 16 + p) * H4 + j];
        }
        if (ks) {
#pragma unroll
            for (int r = 0; r < 16; r++) red_sm[ks - 1][r][c] = acc[r];
        }
        __syncthreads();
        float aval[16];
        if (ks == 0) {
#pragma unroll
            for (int r = 0; r < 16; r++) {
                float a = acc[r] + red_sm[0][r][c] + red_sm[1][r][c] + red_sm[2][r][c];
                a += g_xa[((size_t)t * 64 + n0 + r) * H4 + j];
                aval[r] = a;
            }
        }
        __syncthreads();
        if (ks == 0) {
#pragma unroll
            for (int r = 0; r < 16; r++) red_sm[0][r][c] = aval[r];
        }
        __syncthreads();
        {
            int r = tid >> 4, hl = tid & 15;
            float ai = red_sm[0][r][0 * 16 + hl];
            float af = red_sm[0][r][1 * 16 + hl];
            float ao = red_sm[0][r][2 * 16 + hl];
            float ag = red_sm[0][r][3 * 16 + hl];
            float gi = 1.f / (1.f + expf(-ai));
            float gf = 1.f / (1.f + expf(-af));
            float go = 1.f / (1.f + expf(-ao));
            float gg = tanhf(ag);
            int n = n0 + r, hg = hc0 + hl;
            float cp = g_c[n * HH + hg];          // block-private across steps
            float cn = gf * cp + gi * gg;
            float hn = go * tanhf(cn);
            g_c[n * HH + hg] = cn;
            g_h[wb][n * HH + hg] = hn;
            // fused bf16-split A-operand write for the vocab GEMM (row n*32+t)
            __nv_bfloat16 hi = __float2bfloat16(hn);
            size_t o = (size_t)(n * Tt + t) * HH + hg;
            g_Ah[o] = hi;
            g_Al[o] = __float2bfloat16(hn - __bfloat162float(hi));
        }
        grid_barrier128();
    }
}

// ---------------- K_convB: Wv [512][32000] fp32 -> BhT/BlT [32000][512] bf16-split ----
__global__ void k_convB(const float* __restrict__ Wv) {
    __shared__ float tile[32][33];
    int v0 = blockIdx.x * 32, k0 = blockIdx.y * 32;
    for (int i = threadIdx.y; i < 32; i += 8)
        tile[i][threadIdx.x] = Wv[(size_t)(k0 + i) * VV + v0 + threadIdx.x];
    __syncthreads();
    for (int i = threadIdx.y; i < 32; i += 8) {
        float x = tile[threadIdx.x][i];     // = Wv[k0+tx][v0+i]
        __nv_bfloat16 hi = __float2bfloat16(x);
        float lo = x - __bfloat162float(hi);
        size_t o = (size_t)(v0 + i) * HH + k0 + threadIdx.x;
        g_BhT[o] = hi;
        g_BlT[o] = __float2bfloat16(lo);
    }
}

// ---------------- K5: HMMA bf16-split vocab GEMM ----------------
// D[2048,32000] = hn @ Wv + bv  via  Ah@Bh + Al@Bh + Ah@Bl  (fp32 accum).
// CTA tile 128x128x32, 256 threads (4 M-warps x 2 N-warps, 32x64 per warp),
// cp.async double buffer, 80B SMEM row pitch (conflict-free ldmatrix).
#define VBUF 40960   // bytes per pipeline buffer: AH|AL|BH|BL each 128*80
__global__ __launch_bounds__(256, 1)
void k_vocab_mma(const float* __restrict__ bv, float* __restrict__ out) {
    extern __shared__ char smv[];
    uint32_t sb = smem_u32(smv);
    int tid = threadIdx.x;
    int wid = tid >> 5, lane = tid & 31;
    int warp_m = wid & 3;
    int warp_n = wid >> 2;
    int bm = blockIdx.x, bn = blockIdx.y;

    const __nv_bfloat16* Ah0 = g_Ah + (size_t)bm * 128 * HH;
    const __nv_bfloat16* Al0 = g_Al + (size_t)bm * 128 * HH;
    const __nv_bfloat16* Bh0 = g_BhT + (size_t)bn * 128 * HH;
    const __nv_bfloat16* Bl0 = g_BlT + (size_t)bn * 128 * HH;

    float acc[2][8][4];
#pragma unroll
    for (int a = 0; a < 2; a++)
#pragma unroll
        for (int t = 0; t < 8; t++)
#pragma unroll
            for (int k = 0; k < 4; k++) acc[a][t][k] = 0.f;

    auto issue = [&](int chunk, int b) {
        int k0 = chunk * 32;
        uint32_t base = sb + b * VBUF;
#pragma unroll
        for (int j = 0; j < 2; j++) {
            int idx = tid + j * 256;
            int r = idx >> 2, s = idx & 3;
            uint32_t doff = r * 80 + s * 16;
            size_t goff = (size_t)r * HH + k0 + s * 8;
            cpasync16(base + doff,          Ah0 + goff);
            cpasync16(base + 10240 + doff,  Al0 + goff);
            cpasync16(base + 20480 + doff,  Bh0 + goff);
            cpasync16(base + 30720 + doff,  Bl0 + goff);
        }
        cp_commit();
    };

    issue(0, 0);
    for (int i = 0; i < 16; i++) {
        int b = i & 1;
        if (i < 15) issue(i + 1, b ^ 1);
        if (i < 15) asm volatile("cp.async.wait_group 1;" ::: "memory");
        else        asm volatile("cp.async.wait_group 0;" ::: "memory");
        __syncthreads();

        uint32_t abase = sb + b * VBUF;
#pragma unroll
        for (int kc = 0; kc < 2; kc++) {
            uint32_t ah[2][4], al[2][4], bh[4][4], bl[4][4];
#pragma unroll
            for (int tm = 0; tm < 2; tm++) {
                int row = warp_m * 32 + tm * 16 + (lane & 15);
                uint32_t ad = abase + row * 80 + kc * 32 + (lane >> 4) * 16;
                ldmx4(ah[tm], ad);
                ldmx4(al[tm], ad + 10240);
            }
#pragma unroll
            for (int g = 0; g < 4; g++) {
                int col = warp_n * 64 + g * 16 + (lane & 15);
                uint32_t bd = abase + 20480 + col * 80 + kc * 32 + (lane >> 4) * 16;
                ldmx4(bh[g], bd);
                ldmx4(bl[g], bd + 10240);
            }
#pragma unroll
            for (int tm = 0; tm < 2; tm++)
#pragma unroll
                for (int tn = 0; tn < 8; tn++) {
                    int g = tn >> 1, p = tn & 1;
                    mma16816(acc[tm][tn], ah[tm], bh[g][p], bh[g][p + 2]);
                    mma16816(acc[tm][tn], al[tm], bh[g][p], bh[g][p + 2]);
                    mma16816(acc[tm][tn], ah[tm], bl[g][p], bl[g][p + 2]);
                }
        }
        __syncthreads();
    }

#pragma unroll
    for (int tm = 0; tm < 2; tm++) {
        int row = bm * 128 + warp_m * 32 + tm * 16 + (lane >> 2);
#pragma unroll
        for (int tn = 0; tn < 8; tn++) {
            int col = bn * 128 + warp_n * 64 + tn * 8 + (lane & 3) * 2;
            float b0 = bv[col], b1 = bv[col + 1];
            float2 v0 = make_float2(acc[tm][tn][0] + b0, acc[tm][tn][1] + b1);
            float2 v1 = make_float2(acc[tm][tn][2] + b0, acc[tm][tn][3] + b1);
            *(float2*)&out[(size_t)row * VV + col] = v0;
            *(float2*)&out[(size_t)(row + 8) * VV + col] = v1;
        }
    }
}

// ---------------- launcher ----------------
extern "C" void kernel_launch(void* const* d_in, const int* in_sizes, int n_in,
                              void* d_out, int out_size) {
    const float* A      = (const float*)d_in[0];
    const int*   caps   = (const int*)  d_in[1];
    const float* conv_w = (const float*)d_in[2];
    const float* conv_b = (const float*)d_in[3];
    const float* Wx     = (const float*)d_in[4];
    const float* Wh     = (const float*)d_in[5];
    const float* Wattn  = (const float*)d_in[6];
    const float* b      = (const float*)d_in[7];
    const float* We     = (const float*)d_in[8];
    const float* Wv     = (const float*)d_in[9];
    const float* bv     = (const float*)d_in[10];
    float* out = (float*)d_out;

    cudaFuncSetAttribute(k_vocab_mma, cudaFuncAttributeMaxDynamicSharedMemorySize, 2 * VBUF);

    k_convB<<<dim3(VV / 32, HH / 32), dim3(32, 8)>>>(Wv);
    k_transpose<<<dim3(DA / 32, HH / 32), dim3(32, 8)>>>(conv_w);
    k_conv<<<256, 128>>>(A, conv_b);            // includes h0/c0
    k_xa<<<dim3(16, 64), 128>>>(caps, We, Wx, b);
    k_aw<<<dim3(16, 32), 128>>>(Wattn);
    k_steps<<<128, 256>>>(Wh);                  // all 32 LSTM steps, one launch
    k_vocab_mma<<<dim3(16, 250), 256, 2 * VBUF>>>(bv, out);
}

// round 11
// speedup vs baseline: 1.4448x; 1.4448x over previous
#include <cuda_runtime.h>
#include <cuda_fp16.h>
#include <math.h>
#include <stdint.h>

#define Nn 64
#define Tt 32
#define DA 1280
#define PP 16
#define HH 512
#define H4 2048
#define WD 300
#define VV 32000

// ---------------- device scratch (no allocs allowed) ----------------
__device__ float g_cwT[DA * HH];            // conv_w transposed [c][h]
__device__ float g_Aproj[Nn * PP * HH];     // [n*16+p][512]
__device__ float g_h[2][Nn * HH];           // double-buffered h
__device__ float g_c[Nn * HH];
__device__ float g_w[Nn * PP];              // attention weights for current step
__device__ float g_xa[Tt * Nn * H4];        // x@Wx + b, row r = t*64+n
__device__ float g_AW[Nn * PP * H4];        // Aproj@Wattn, [n*16+p][2048]

// fp16 operands for the HMMA vocab GEMM (K-major)
__device__ __align__(16) __half g_Ah[Nn * Tt * HH];       // [2048][512], row n*32+t
__device__ __align__(16) __half g_BhT[(size_t)VV * HH];   // [32000][512]

// ---------------- portable PTX helpers (sm_80+ features only) ----------------
__device__ __forceinline__ uint32_t smem_u32(const void* p) {
    uint32_t a;
    asm("{ .reg .u64 t; cvta.to.shared.u64 t, %1; cvt.u32.u64 %0, t; }" : "=r"(a) : "l"(p));
    return a;
}
__device__ __forceinline__ void cpasync16(uint32_t dst, const void* src) {
    asm volatile("cp.async.cg.shared.global [%0], [%1], 16;" :: "r"(dst), "l"(src) : "memory");
}
__device__ __forceinline__ void cp_commit() {
    asm volatile("cp.async.commit_group;" ::: "memory");
}
__device__ __forceinline__ void ldmx4(uint32_t* r, uint32_t addr) {
    asm volatile("ldmatrix.sync.aligned.m8n8.x4.shared.b16 {%0,%1,%2,%3}, [%4];"
                 : "=r"(r[0]), "=r"(r[1]), "=r"(r[2]), "=r"(r[3]) : "r"(addr));
}
__device__ __forceinline__ void mma16816h(float* d, const uint32_t* a, uint32_t b0, uint32_t b1) {
    asm volatile(
        "mma.sync.aligned.m16n8k16.row.col.f32.f16.f16.f32 "
        "{%0,%1,%2,%3}, {%4,%5,%6,%7}, {%8,%9}, {%0,%1,%2,%3};"
        : "+f"(d[0]), "+f"(d[1]), "+f"(d[2]), "+f"(d[3])
        : "r"(a[0]), "r"(a[1]), "r"(a[2]), "r"(a[3]), "r"(b0), "r"(b1));
}

// ---------------- K0: transpose conv_w [512][1280] -> g_cwT [1280][512] ----------------
__global__ void k_transpose(const float* __restrict__ w) {
    __shared__ float tile[32][33];
    int c0 = blockIdx.x * 32, h0 = blockIdx.y * 32;
    for (int i = threadIdx.y; i < 32; i += 8)
        tile[i][threadIdx.x] = w[(h0 + i) * DA + c0 + threadIdx.x];
    __syncthreads();
    for (int i = threadIdx.y; i < 32; i += 8)
        g_cwT[(c0 + i) * HH + h0 + threadIdx.x] = tile[threadIdx.x][i];
}

// ---------------- K1: Aproj + fused h0/c0 ----------------
__global__ void k_conv(const float* __restrict__ A, const float* __restrict__ cb) {
    int n = blockIdx.x >> 2, cg = blockIdx.x & 3;
    int j = cg * 128 + threadIdx.x;
    __shared__ float a_sm[256 * 16];
    float acc[16];
#pragma unroll
    for (int p = 0; p < 16; p++) acc[p] = 0.f;
    for (int k0 = 0; k0 < DA; k0 += 256) {
        __syncthreads();
        const float* src = A + ((size_t)n * DA + k0) * 16;
        for (int idx = threadIdx.x; idx < 256 * 16; idx += 128) a_sm[idx] = src[idx];
        __syncthreads();
#pragma unroll 4
        for (int kk = 0; kk < 256; kk++) {
            float w = g_cwT[(k0 + kk) * HH + j];
            const float4* ar = (const float4*)&a_sm[kk * 16];
            float4 a0 = ar[0], a1 = ar[1], a2 = ar[2], a3 = ar[3];
            acc[0]  += a0.x * w; acc[1]  += a0.y * w; acc[2]  += a0.z * w; acc[3]  += a0.w * w;
            acc[4]  += a1.x * w; acc[5]  += a1.y * w; acc[6]  += a1.z * w; acc[7]  += a1.w * w;
            acc[8]  += a2.x * w; acc[9]  += a2.y * w; acc[10] += a2.z * w; acc[11] += a2.w * w;
            acc[12] += a3.x * w; acc[13] += a3.y * w; acc[14] += a3.z * w; acc[15] += a3.w * w;
        }
    }
    float bb = cb[j];
    float s = 0.f;
#pragma unroll
    for (int p = 0; p < 16; p++) {
        g_Aproj[(n * 16 + p) * HH + j] = acc[p] + bb;
        s += acc[p];
    }
    s = s * (1.f / 16.f) + bb;          // mean_p(acc[p] + bb)
    g_h[0][n * HH + j] = s;
    g_c[n * HH + j] = s;
}

// ---------------- K2: xa[r][j] = emb(cap)[r] @ Wx + b, r = t*64+n ----------------
// prefetch distance 2 on the strided Wx loads (MLP 8)
__global__ void k_xa(const int* __restrict__ caps, const float* __restrict__ We,
                     const float* __restrict__ Wx, const float* __restrict__ bias) {
    int col = blockIdx.x * 128 + threadIdx.x;
    int r0 = blockIdx.y * 32;
    __shared__ int tok[32];
    __shared__ float x_sm[32 * 304];
    if (threadIdx.x < 32) {
        int rr = r0 + threadIdx.x;
        int n = rr & 63, t = rr >> 6;
        tok[threadIdx.x] = caps[n * Tt + t];
    }
    __syncthreads();
    for (int idx = threadIdx.x; idx < 32 * 300; idx += 128) {
        int r = idx / 300, c = idx - r * 300;
        x_sm[r * 304 + c] = We[(size_t)tok[r] * 300 + c];
    }
    __syncthreads();
    float acc[32];
#pragma unroll
    for (int r = 0; r < 32; r++) acc[r] = 0.f;
    float c0 = Wx[col], c1 = Wx[H4 + col], c2 = Wx[2 * H4 + col], c3 = Wx[3 * H4 + col];
    const float* wp1 = Wx + (size_t)4 * H4 + col;
    float p0 = wp1[0], p1 = wp1[H4], p2 = wp1[2 * H4], p3 = wp1[3 * H4];
    for (int k0 = 0; k0 < 300; k0 += 4) {
        float m0 = 0.f, m1 = 0.f, m2 = 0.f, m3 = 0.f;
        if (k0 + 8 < 300) {
            const float* wp = Wx + (size_t)(k0 + 8) * H4 + col;
            m0 = wp[0]; m1 = wp[H4]; m2 = wp[2 * H4]; m3 = wp[3 * H4];
        }
#pragma unroll
        for (int r = 0; r < 32; r++) {
            float4 xv = *(const float4*)&x_sm[r * 304 + k0];
            acc[r] += xv.x * c0 + xv.y * c1 + xv.z * c2 + xv.w * c3;
        }
        c0 = p0; c1 = p1; c2 = p2; c3 = p3;
        p0 = m0; p1 = m1; p2 = m2; p3 = m3;
    }
    float bb = bias[col];
#pragma unroll
    for (int r = 0; r < 32; r++) g_xa[(size_t)(r0 + r) * H4 + col] = acc[r] + bb;
}

// ---------------- K3: AW[r][j] = Aproj[r][:] @ Wattn, r = n*16+p ----------------
__global__ void k_aw(const float* __restrict__ Wattn) {
    int col = blockIdx.x * 128 + threadIdx.x;
    int r0 = blockIdx.y * 32;
    __shared__ float a_sm[32 * 256];
    float acc[32];
#pragma unroll
    for (int r = 0; r < 32; r++) acc[r] = 0.f;
    for (int k0 = 0; k0 < HH; k0 += 256) {
        __syncthreads();
        for (int idx = threadIdx.x; idx < 32 * 256; idx += 128) {
            int r = idx >> 8, c = idx & 255;
            a_sm[idx] = g_Aproj[(r0 + r) * HH + k0 + c];
        }
        __syncthreads();
        for (int kk = 0; kk < 256; kk += 4) {
            float w0 = Wattn[(k0 + kk + 0) * H4 + col];
            float w1 = Wattn[(k0 + kk + 1) * H4 + col];
            float w2 = Wattn[(k0 + kk + 2) * H4 + col];
            float w3 = Wattn[(k0 + kk + 3) * H4 + col];
#pragma unroll
            for (int r = 0; r < 32; r++) {
                float4 av = *(const float4*)&a_sm[r * 256 + kk];
                acc[r] += av.x * w0 + av.y * w1 + av.z * w2 + av.w * w3;
            }
        }
    }
#pragma unroll
    for (int r = 0; r < 32; r++) g_AW[(size_t)(r0 + r) * H4 + col] = acc[r];
}

// ---------------- K4a: attention weights for step t ----------------
__global__ void k_attw(int t) {
    int rb = t & 1;
    int n = blockIdx.x;
    int tid = threadIdx.x;
    int p = tid >> 4, l = tid & 15;
    __shared__ float sc[16];
    const float* hv = g_h[rb] + n * HH;
    const float* av = g_Aproj + (n * 16 + p) * HH;
    float s = 0.f;
#pragma unroll 8
    for (int i = 0; i < 32; i++) {
        int k = l + i * 16;
        s += hv[k] * av[k];
    }
    s += __shfl_down_sync(0xffffffffu, s, 8, 16);
    s += __shfl_down_sync(0xffffffffu, s, 4, 16);
    s += __shfl_down_sync(0xffffffffu, s, 2, 16);
    s += __shfl_down_sync(0xffffffffu, s, 1, 16);
    if (l == 0) sc[p] = s * 0.04419417382415922f;  // 1/sqrt(512)
    __syncthreads();
    if (tid < 16) {
        float v = sc[tid];
        float m = v;
        for (int off = 8; off; off >>= 1) m = fmaxf(m, __shfl_xor_sync(0x0000ffffu, m, off, 16));
        float e = expf(v - m);
        float sum = e;
        for (int off = 8; off; off >>= 1) sum += __shfl_xor_sync(0x0000ffffu, sum, off, 16);
        g_w[n * 16 + tid] = e / sum;
    }
}

// ---------------- K4b: fused LSTM step (R9-proven structure) ----------------
__global__ void k_step(const float* __restrict__ Wh, int t) {
    int rb = t & 1, wb = rb ^ 1;
    int hc0 = blockIdx.x * 16;
    int n0 = blockIdx.y * 16;
    __shared__ float h_sm[16][512];
    __shared__ float red_sm[3][16][64];
    __shared__ float w_sm[16][16];
    int tid = threadIdx.x;
    for (int idx = tid; idx < 16 * 512; idx += 256) {
        int r = idx >> 9, k = idx & 511;
        h_sm[r][k] = g_h[rb][(n0 + r) * HH + k];
    }
    w_sm[tid >> 4][tid & 15] = g_w[(n0 + (tid >> 4)) * 16 + (tid & 15)];
    __syncthreads();

    int c = tid & 63;
    int ks = tid >> 6;
    int gate = c >> 4, hcl = c & 15;
    int j = gate * HH + hc0 + hcl;
    const float* whcol = Wh + j;

    float acc[16];
#pragma unroll
    for (int r = 0; r < 16; r++) acc[r] = 0.f;

    int kbeg = ks * 128;
    for (int k = kbeg; k < kbeg + 128; k += 4) {
        float w0 = whcol[(k + 0) * H4];
        float w1 = whcol[(k + 1) * H4];
        float w2 = whcol[(k + 2) * H4];
        float w3 = whcol[(k + 3) * H4];
#pragma unroll
        for (int r = 0; r < 16; r++) {
            float4 h4 = *(const float4*)&h_sm[r][k];
            acc[r] += h4.x * w0 + h4.y * w1 + h4.z * w2 + h4.w * w3;
        }
    }
#pragma unroll
    for (int pp = 0; pp < 4; pp++) {
        int p = ks * 4 + pp;
#pragma unroll
        for (int r = 0; r < 16; r++)
            acc[r] += w_sm[r][p] * g_AW[((size_t)(n0 + r) * 16 + p) * H4 + j];
    }
    if (ks) {
#pragma unroll
        for (int r = 0; r < 16; r++) red_sm[ks - 1][r][c] = acc[r];
    }
    __syncthreads();
    float aval[16];
    if (ks == 0) {
#pragma unroll
        for (int r = 0; r < 16; r++) {
            float a = acc[r] + red_sm[0][r][c] + red_sm[1][r][c] + red_sm[2][r][c];
            a += g_xa[((size_t)t * 64 + n0 + r) * H4 + j];
            aval[r] = a;
        }
    }
    __syncthreads();
    if (ks == 0) {
#pragma unroll
        for (int r = 0; r < 16; r++) red_sm[0][r][c] = aval[r];
    }
    __syncthreads();
    {
        int r = tid >> 4, hl = tid & 15;
        float ai = red_sm[0][r][0 * 16 + hl];
        float af = red_sm[0][r][1 * 16 + hl];
        float ao = red_sm[0][r][2 * 16 + hl];
        float ag = red_sm[0][r][3 * 16 + hl];
        float gi = 1.f / (1.f + expf(-ai));
        float gf = 1.f / (1.f + expf(-af));
        float go = 1.f / (1.f + expf(-ao));
        float gg = tanhf(ag);
        int ng = n0 + r, hg = hc0 + hl;
        float cp = g_c[ng * HH + hg];
        float cn = gf * cp + gi * gg;
        float hn = go * tanhf(cn);
        g_c[ng * HH + hg] = cn;
        g_h[wb][ng * HH + hg] = hn;
        // fused fp16 A-operand write for the vocab GEMM (row n*32+t)
        g_Ah[(size_t)(ng * Tt + t) * HH + hg] = __float2half(hn);
    }
}

// ---------------- K_convB: Wv [512][32000] fp32 -> g_BhT [32000][512] fp16 ----------
__global__ void k_convB(const float* __restrict__ Wv) {
    __shared__ float tile[32][33];
    int v0 = blockIdx.x * 32, k0 = blockIdx.y * 32;
    for (int i = threadIdx.y; i < 32; i += 8)
        tile[i][threadIdx.x] = Wv[(size_t)(k0 + i) * VV + v0 + threadIdx.x];
    __syncthreads();
    for (int i = threadIdx.y; i < 32; i += 8)
        g_BhT[(size_t)(v0 + i) * HH + k0 + threadIdx.x] = __float2half(tile[threadIdx.x][i]);
}

// ---------------- K5: fp16 HMMA vocab GEMM ----------------
// D[2048,32000] = hn @ Wv + bv, single fp16 product, fp32 accum.
// CTA tile 128x128x32, 256 threads (4 M-warps x 2 N-warps, 32x64 per warp),
// cp.async double buffer, 80B SMEM row pitch (conflict-free ldmatrix).
#define VBUF 20480   // bytes per pipeline buffer: A(128*80) | B(128*80)
__global__ __launch_bounds__(256)
void k_vocab_mma(const float* __restrict__ bv, float* __restrict__ out) {
    extern __shared__ char smv[];
    uint32_t sb = smem_u32(smv);
    int tid = threadIdx.x;
    int wid = tid >> 5, lane = tid & 31;
    int warp_m = wid & 3;
    int warp_n = wid >> 2;
    int bm = blockIdx.x, bn = blockIdx.y;

    const __half* Ah0 = g_Ah + (size_t)bm * 128 * HH;
    const __half* Bh0 = g_BhT + (size_t)bn * 128 * HH;

    float acc[2][8][4];
#pragma unroll
    for (int a = 0; a < 2; a++)
#pragma unroll
        for (int t = 0; t < 8; t++)
#pragma unroll
            for (int k = 0; k < 4; k++) acc[a][t][k] = 0.f;

    auto issue = [&](int chunk, int b) {
        int k0 = chunk * 32;
        uint32_t base = sb + b * VBUF;
#pragma unroll
        for (int j = 0; j < 2; j++) {
            int idx = tid + j * 256;        // 0..511
            int r = idx >> 2, s = idx & 3;  // row, 16B-slice
            uint32_t doff = r * 80 + s * 16;
            size_t goff = (size_t)r * HH + k0 + s * 8;
            cpasync16(base + doff,          Ah0 + goff);
            cpasync16(base + 10240 + doff,  Bh0 + goff);
        }
        cp_commit();
    };

    issue(0, 0);
    for (int i = 0; i < 16; i++) {
        int b = i & 1;
        if (i < 15) issue(i + 1, b ^ 1);
        if (i < 15) asm volatile("cp.async.wait_group 1;" ::: "memory");
        else        asm volatile("cp.async.wait_group 0;" ::: "memory");
        __syncthreads();

        uint32_t abase = sb + b * VBUF;
#pragma unroll
        for (int kc = 0; kc < 2; kc++) {
            uint32_t ah[2][4], bh[4][4];
#pragma unroll
            for (int tm = 0; tm < 2; tm++) {
                int row = warp_m * 32 + tm * 16 + (lane & 15);
                ldmx4(ah[tm], abase + row * 80 + kc * 32 + (lane >> 4) * 16);
            }
#pragma unroll
            for (int g = 0; g < 4; g++) {
                int col = warp_n * 64 + g * 16 + (lane & 15);
                ldmx4(bh[g], abase + 10240 + col * 80 + kc * 32 + (lane >> 4) * 16);
            }
#pragma unroll
            for (int tm = 0; tm < 2; tm++)
#pragma unroll
                for (int tn = 0; tn < 8; tn++) {
                    int g = tn >> 1, p = tn & 1;
                    mma16816h(acc[tm][tn], ah[tm], bh[g][p], bh[g][p + 2]);
                }
        }
        __syncthreads();
    }

#pragma unroll
    for (int tm = 0; tm < 2; tm++) {
        int row = bm * 128 + warp_m * 32 + tm * 16 + (lane >> 2);
#pragma unroll
        for (int tn = 0; tn < 8; tn++) {
            int col = bn * 128 + warp_n * 64 + tn * 8 + (lane & 3) * 2;
            float b0 = bv[col], b1 = bv[col + 1];
            float2 v0 = make_float2(acc[tm][tn][0] + b0, acc[tm][tn][1] + b1);
            float2 v1 = make_float2(acc[tm][tn][2] + b0, acc[tm][tn][3] + b1);
            *(float2*)&out[(size_t)row * VV + col] = v0;
            *(float2*)&out[(size_t)(row + 8) * VV + col] = v1;
        }
    }
}

// ---------------- launcher ----------------
extern "C" void kernel_launch(void* const* d_in, const int* in_sizes, int n_in,
                              void* d_out, int out_size) {
    const float* A      = (const float*)d_in[0];
    const int*   caps   = (const int*)  d_in[1];
    const float* conv_w = (const float*)d_in[2];
    const float* conv_b = (const float*)d_in[3];
    const float* Wx     = (const float*)d_in[4];
    const float* Wh     = (const float*)d_in[5];
    const float* Wattn  = (const float*)d_in[6];
    const float* b      = (const float*)d_in[7];
    const float* We     = (const float*)d_in[8];
    const float* Wv     = (const float*)d_in[9];
    const float* bv     = (const float*)d_in[10];
    float* out = (float*)d_out;

    cudaFuncSetAttribute(k_vocab_mma, cudaFuncAttributeMaxDynamicSharedMemorySize, 2 * VBUF);

    k_convB<<<dim3(VV / 32, HH / 32), dim3(32, 8)>>>(Wv);
    k_transpose<<<dim3(DA / 32, HH / 32), dim3(32, 8)>>>(conv_w);
    k_conv<<<256, 128>>>(A, conv_b);            // includes h0/c0
    k_xa<<<dim3(16, 64), 128>>>(caps, We, Wx, b);
    k_aw<<<dim3(16, 32), 128>>>(Wattn);
    for (int t = 0; t < Tt; t++) {
        k_attw<<<Nn, 256>>>(t);
        k_step<<<dim3(32, 4), 256>>>(Wh, t);
    }
    k_vocab_mma<<<dim3(16, 250), 256, 2 * VBUF>>>(bv, out);
}

// round 12
// speedup vs baseline: 1.4765x; 1.0220x over previous
#include <cuda_runtime.h>
#include <cuda_fp16.h>
#include <cuda_bf16.h>
#include <math.h>
#include <stdint.h>

#define Nn 64
#define Tt 32
#define DA 1280
#define PP 16
#define HH 512
#define H4 2048
#define WD 300
#define KXP 320     // Wx K padded 300 -> 320
#define VV 32000

// ---------------- device scratch (no allocs allowed) ----------------
__device__ float g_cwT[DA * HH];            // conv_w transposed [c][h]
__device__ float g_Aproj[Nn * PP * HH];     // [n*16+p][512] fp32 (attention dots)
__device__ float g_h[2][Nn * HH];           // double-buffered h
__device__ float g_c[Nn * HH];
__device__ float g_w[Nn * PP];              // attention weights for current step
__device__ float g_xa[Tt * Nn * H4];        // x@Wx + b, row r = t*64+n
__device__ float g_AW[Nn * PP * H4];        // Aproj@Wattn, [n*16+p][2048]
__device__ unsigned int g_wflag[Tt * 4];    // per (step, n-group) producer flags

// fp16 operands for the vocab GEMM (K-major)
__device__ __align__(16) __half g_Ah[Nn * Tt * HH];       // [2048][512], row n*32+t
__device__ __align__(16) __half g_BhT[(size_t)VV * HH];   // [32000][512]

// bf16-split operands for the xa / aw HMMA GEMMs (K-major)
__device__ __align__(16) __nv_bfloat16 g_Axh[Tt * Nn * KXP];   // gathered x, [2048][320]
__device__ __align__(16) __nv_bfloat16 g_Axl[Tt * Nn * KXP];
__device__ __align__(16) __nv_bfloat16 g_WxTh[H4 * KXP];       // Wx^T, [2048][320]
__device__ __align__(16) __nv_bfloat16 g_WxTl[H4 * KXP];
__device__ __align__(16) __nv_bfloat16 g_WaTh[H4 * HH];        // Wattn^T, [2048][512]
__device__ __align__(16) __nv_bfloat16 g_WaTl[H4 * HH];
__device__ __align__(16) __nv_bfloat16 g_APh[Nn * PP * HH];    // Aproj split, [1024][512]
__device__ __align__(16) __nv_bfloat16 g_APl[Nn * PP * HH];

// ---------------- portable PTX helpers (sm_80+ features only) ----------------
__device__ __forceinline__ uint32_t smem_u32(const void* p) {
    uint32_t a;
    asm("{ .reg .u64 t; cvta.to.shared.u64 t, %1; cvt.u32.u64 %0, t; }" : "=r"(a) : "l"(p));
    return a;
}
__device__ __forceinline__ void cpasync16(uint32_t dst, const void* src) {
    asm volatile("cp.async.cg.shared.global [%0], [%1], 16;" :: "r"(dst), "l"(src) : "memory");
}
__device__ __forceinline__ void cp_commit() {
    asm volatile("cp.async.commit_group;" ::: "memory");
}
__device__ __forceinline__ void ldmx4(uint32_t* r, uint32_t addr) {
    asm volatile("ldmatrix.sync.aligned.m8n8.x4.shared.b16 {%0,%1,%2,%3}, [%4];"
                 : "=r"(r[0]), "=r"(r[1]), "=r"(r[2]), "=r"(r[3]) : "r"(addr));
}
__device__ __forceinline__ void mma16816h(float* d, const uint32_t* a, uint32_t b0, uint32_t b1) {
    asm volatile(
        "mma.sync.aligned.m16n8k16.row.col.f32.f16.f16.f32 "
        "{%0,%1,%2,%3}, {%4,%5,%6,%7}, {%8,%9}, {%0,%1,%2,%3};"
        : "+f"(d[0]), "+f"(d[1]), "+f"(d[2]), "+f"(d[3])
        : "r"(a[0]), "r"(a[1]), "r"(a[2]), "r"(a[3]), "r"(b0), "r"(b1));
}
__device__ __forceinline__ void mma16816b(float* d, const uint32_t* a, uint32_t b0, uint32_t b1) {
    asm volatile(
        "mma.sync.aligned.m16n8k16.row.col.f32.bf16.bf16.f32 "
        "{%0,%1,%2,%3}, {%4,%5,%6,%7}, {%8,%9}, {%0,%1,%2,%3};"
        : "+f"(d[0]), "+f"(d[1]), "+f"(d[2]), "+f"(d[3])
        : "r"(a[0]), "r"(a[1]), "r"(a[2]), "r"(a[3]), "r"(b0), "r"(b1));
}

// ---------------- K_init: zero producer flags (every launch -> replay-safe) ----------
__global__ void k_initflags() {
    if (threadIdx.x < Tt * 4) g_wflag[threadIdx.x] = 0u;
}

// ---------------- K0: transpose conv_w [512][1280] -> g_cwT [1280][512] ----------------
__global__ void k_transpose(const float* __restrict__ w) {
    __shared__ float tile[32][33];
    int c0 = blockIdx.x * 32, h0 = blockIdx.y * 32;
    for (int i = threadIdx.y; i < 32; i += 8)
        tile[i][threadIdx.x] = w[(h0 + i) * DA + c0 + threadIdx.x];
    __syncthreads();
    for (int i = threadIdx.y; i < 32; i += 8)
        g_cwT[(c0 + i) * HH + h0 + threadIdx.x] = tile[threadIdx.x][i];
}

// ---------------- K1: Aproj (fp32 + bf16-split) + fused h0/c0 ----------------
__global__ void k_conv(const float* __restrict__ A, const float* __restrict__ cb) {
    int n = blockIdx.x >> 2, cg = blockIdx.x & 3;
    int j = cg * 128 + threadIdx.x;
    __shared__ float a_sm[256 * 16];
    float acc[16];
#pragma unroll
    for (int p = 0; p < 16; p++) acc[p] = 0.f;
    for (int k0 = 0; k0 < DA; k0 += 256) {
        __syncthreads();
        const float* src = A + ((size_t)n * DA + k0) * 16;
        for (int idx = threadIdx.x; idx < 256 * 16; idx += 128) a_sm[idx] = src[idx];
        __syncthreads();
#pragma unroll 4
        for (int kk = 0; kk < 256; kk++) {
            float w = g_cwT[(k0 + kk) * HH + j];
            const float4* ar = (const float4*)&a_sm[kk * 16];
            float4 a0 = ar[0], a1 = ar[1], a2 = ar[2], a3 = ar[3];
            acc[0]  += a0.x * w; acc[1]  += a0.y * w; acc[2]  += a0.z * w; acc[3]  += a0.w * w;
            acc[4]  += a1.x * w; acc[5]  += a1.y * w; acc[6]  += a1.z * w; acc[7]  += a1.w * w;
            acc[8]  += a2.x * w; acc[9]  += a2.y * w; acc[10] += a2.z * w; acc[11] += a2.w * w;
            acc[12] += a3.x * w; acc[13] += a3.y * w; acc[14] += a3.z * w; acc[15] += a3.w * w;
        }
    }
    float bb = cb[j];
    float s = 0.f;
#pragma unroll
    for (int p = 0; p < 16; p++) {
        float v = acc[p] + bb;
        size_t o = (size_t)(n * 16 + p) * HH + j;
        g_Aproj[o] = v;
        __nv_bfloat16 hi = __float2bfloat16(v);
        g_APh[o] = hi;
        g_APl[o] = __float2bfloat16(v - __bfloat162float(hi));
        s += acc[p];
    }
    s = s * (1.f / 16.f) + bb;          // mean_p(acc[p] + bb)
    g_h[0][n * HH + j] = s;
    g_c[n * HH + j] = s;
}

// ---------------- K_convWx: Wx [300][2048] -> WxT hi/lo [2048][320] (zero-pad K) ------
__global__ void k_convWx(const float* __restrict__ Wx) {
    __shared__ float tile[32][33];
    int j0 = blockIdx.x * 32, k0 = blockIdx.y * 32;
    for (int i = threadIdx.y; i < 32; i += 8) {
        int k = k0 + i;
        tile[i][threadIdx.x] = (k < WD) ? Wx[(size_t)k * H4 + j0 + threadIdx.x] : 0.f;
    }
    __syncthreads();
    for (int i = threadIdx.y; i < 32; i += 8) {
        float x = tile[threadIdx.x][i];   // = Wx[k0+tx][j0+i]
        __nv_bfloat16 hi = __float2bfloat16(x);
        size_t o = (size_t)(j0 + i) * KXP + k0 + threadIdx.x;
        g_WxTh[o] = hi;
        g_WxTl[o] = __float2bfloat16(x - __bfloat162float(hi));
    }
}

// ---------------- K_convWa: Wattn [512][2048] -> WaT hi/lo [2048][512] ----------------
__global__ void k_convWa(const float* __restrict__ Wa) {
    __shared__ float tile[32][33];
    int j0 = blockIdx.x * 32, k0 = blockIdx.y * 32;
    for (int i = threadIdx.y; i < 32; i += 8)
        tile[i][threadIdx.x] = Wa[(size_t)(k0 + i) * H4 + j0 + threadIdx.x];
    __syncthreads();
    for (int i = threadIdx.y; i < 32; i += 8) {
        float x = tile[threadIdx.x][i];
        __nv_bfloat16 hi = __float2bfloat16(x);
        size_t o = (size_t)(j0 + i) * HH + k0 + threadIdx.x;
        g_WaTh[o] = hi;
        g_WaTl[o] = __float2bfloat16(x - __bfloat162float(hi));
    }
}

// ---------------- K_gatherX: x[r][c] = We[tok[r]][c] -> bf16 split, r = t*64+n --------
__global__ void k_gatherX(const int* __restrict__ caps, const float* __restrict__ We) {
    int idx = blockIdx.x * 256 + threadIdx.x;
    int r = idx / KXP, c = idx - r * KXP;
    int n = r & 63, t = r >> 6;
    float v = 0.f;
    if (c < WD) v = We[(size_t)caps[n * Tt + t] * WD + c];
    __nv_bfloat16 hi = __float2bfloat16(v);
    g_Axh[idx] = hi;
    g_Axl[idx] = __float2bfloat16(v - __bfloat162float(hi));
}

// ---------------- K_gemm3: generic bf16-split 3-product HMMA GEMM ----------------
// out[M,N] = A @ B^T (+bias); A,B K-major bf16 hi/lo; which: 0 = xa, 1 = aw.
// CTA tile 128x128, 256 threads, cp.async double buffer, 80B pitch (R9-proven).
#define VBUF3 40960
__global__ __launch_bounds__(256)
void k_gemm3(int which, const float* __restrict__ bias, int K, int ldo) {
    const __nv_bfloat16 *Ahp, *Alp, *Bhp, *Blp;
    float* out;
    if (which == 0) { Ahp = g_Axh; Alp = g_Axl; Bhp = g_WxTh; Blp = g_WxTl; out = g_xa; }
    else            { Ahp = g_APh; Alp = g_APl; Bhp = g_WaTh; Blp = g_WaTl; out = g_AW; }

    extern __shared__ char smv[];
    uint32_t sb = smem_u32(smv);
    int tid = threadIdx.x;
    int wid = tid >> 5, lane = tid & 31;
    int warp_m = wid & 3, warp_n = wid >> 2;
    int bm = blockIdx.x, bn = blockIdx.y;

    const __nv_bfloat16* Ah0 = Ahp + (size_t)bm * 128 * K;
    const __nv_bfloat16* Al0 = Alp + (size_t)bm * 128 * K;
    const __nv_bfloat16* Bh0 = Bhp + (size_t)bn * 128 * K;
    const __nv_bfloat16* Bl0 = Blp + (size_t)bn * 128 * K;

    float acc[2][8][4];
#pragma unroll
    for (int a = 0; a < 2; a++)
#pragma unroll
        for (int t = 0; t < 8; t++)
#pragma unroll
            for (int k = 0; k < 4; k++) acc[a][t][k] = 0.f;

    int chunks = K >> 5;
    auto issue = [&](int chunk, int b) {
        int k0 = chunk * 32;
        uint32_t base = sb + b * VBUF3;
#pragma unroll
        for (int j = 0; j < 2; j++) {
            int idx = tid + j * 256;
            int r = idx >> 2, s = idx & 3;
            uint32_t doff = r * 80 + s * 16;
            size_t goff = (size_t)r * K + k0 + s * 8;
            cpasync16(base + doff,          Ah0 + goff);
            cpasync16(base + 10240 + doff,  Al0 + goff);
            cpasync16(base + 20480 + doff,  Bh0 + goff);
            cpasync16(base + 30720 + doff,  Bl0 + goff);
        }
        cp_commit();
    };

    issue(0, 0);
    for (int i = 0; i < chunks; i++) {
        int b = i & 1;
        if (i < chunks - 1) issue(i + 1, b ^ 1);
        if (i < chunks - 1) asm volatile("cp.async.wait_group 1;" ::: "memory");
        else                asm volatile("cp.async.wait_group 0;" ::: "memory");
        __syncthreads();

        uint32_t abase = sb + b * VBUF3;
#pragma unroll
        for (int kc = 0; kc < 2; kc++) {
            uint32_t ah[2][4], al[2][4], bh[4][4], bl[4][4];
#pragma unroll
            for (int tm = 0; tm < 2; tm++) {
                int row = warp_m * 32 + tm * 16 + (lane & 15);
                uint32_t ad = abase + row * 80 + kc * 32 + (lane >> 4) * 16;
                ldmx4(ah[tm], ad);
                ldmx4(al[tm], ad + 10240);
            }
#pragma unroll
            for (int g = 0; g < 4; g++) {
                int col = warp_n * 64 + g * 16 + (lane & 15);
                uint32_t bd = abase + 20480 + col * 80 + kc * 32 + (lane >> 4) * 16;
                ldmx4(bh[g], bd);
                ldmx4(bl[g], bd + 10240);
            }
#pragma unroll
            for (int tm = 0; tm < 2; tm++)
#pragma unroll
                for (int tn = 0; tn < 8; tn++) {
                    int g = tn >> 1, p = tn & 1;
                    mma16816b(acc[tm][tn], ah[tm], bh[g][p], bh[g][p + 2]);
                    mma16816b(acc[tm][tn], al[tm], bh[g][p], bh[g][p + 2]);
                    mma16816b(acc[tm][tn], ah[tm], bl[g][p], bl[g][p + 2]);
                }
        }
        __syncthreads();
    }

#pragma unroll
    for (int tm = 0; tm < 2; tm++) {
        int row = bm * 128 + warp_m * 32 + tm * 16 + (lane >> 2);
#pragma unroll
        for (int tn = 0; tn < 8; tn++) {
            int col = bn * 128 + warp_n * 64 + tn * 8 + (lane & 3) * 2;
            float b0 = bias ? bias[col] : 0.f;
            float b1 = bias ? bias[col + 1] : 0.f;
            float2 v0 = make_float2(acc[tm][tn][0] + b0, acc[tm][tn][1] + b1);
            float2 v1 = make_float2(acc[tm][tn][2] + b0, acc[tm][tn][3] + b1);
            *(float2*)&out[(size_t)row * ldo + col] = v0;
            *(float2*)&out[(size_t)(row + 8) * ldo + col] = v1;
        }
    }
}

// ---------------- K4: fused LSTM step (attw producers in same launch) ----------------
// grid (33, 4): bx<32 = consumer (hc-group), bx==32 = attention producer for n-group by.
__global__ void k_step(const float* __restrict__ Wh, int t) {
    int rb = t & 1, wb = rb ^ 1;
    int ng = blockIdx.y;
    int n0 = ng * 16;
    int tid = threadIdx.x;

    if (blockIdx.x == 32) {
        // ---- producer: attention weights for this n-group ----
        int n_l = tid >> 4, p = tid & 15;
        int n = n0 + n_l;
        const float4* hp = (const float4*)(g_h[rb] + (size_t)n * HH);
        const float4* ap = (const float4*)(g_Aproj + (size_t)(n * 16 + p) * HH);
        float s = 0.f;
#pragma unroll 8
        for (int i = 0; i < 128; i++) {
            float4 h4 = hp[i], a4 = ap[i];
            s += h4.x * a4.x + h4.y * a4.y + h4.z * a4.z + h4.w * a4.w;
        }
        s *= 0.04419417382415922f;  // 1/sqrt(512)
        float m = s;
        for (int off = 8; off; off >>= 1)
            m = fmaxf(m, __shfl_xor_sync(0xffffffffu, m, off, 16));
        float e = expf(s - m);
        float sum = e;
        for (int off = 8; off; off >>= 1)
            sum += __shfl_xor_sync(0xffffffffu, sum, off, 16);
        g_w[n * 16 + p] = e / sum;
        __threadfence();
        __syncthreads();
        if (tid == 0) *((volatile unsigned int*)&g_wflag[t * 4 + ng]) = 1u;
        return;
    }

    // ---- consumer ----
    int hc0 = blockIdx.x * 16;
    __shared__ float h_sm[16][512];
    __shared__ float red_sm[3][16][64];
    __shared__ float w_sm[16][16];
    for (int idx = tid; idx < 16 * 512; idx += 256) {
        int r = idx >> 9, k = idx & 511;
        h_sm[r][k] = g_h[rb][(n0 + r) * HH + k];
    }
    __syncthreads();

    int c = tid & 63;
    int ks = tid >> 6;
    int gate = c >> 4, hcl = c & 15;
    int j = gate * HH + hc0 + hcl;
    const float* whcol = Wh + j;

    float acc[16];
#pragma unroll
    for (int r = 0; r < 16; r++) acc[r] = 0.f;

    int kbeg = ks * 128;
    for (int k = kbeg; k < kbeg + 128; k += 4) {
        float w0 = whcol[(k + 0) * H4];
        float w1 = whcol[(k + 1) * H4];
        float w2 = whcol[(k + 2) * H4];
        float w3 = whcol[(k + 3) * H4];
#pragma unroll
        for (int r = 0; r < 16; r++) {
            float4 h4 = *(const float4*)&h_sm[r][k];
            acc[r] += h4.x * w0 + h4.y * w1 + h4.z * w2 + h4.w * w3;
        }
    }

    // wait for this step's attention weights (plain volatile poll — no atomics)
    if (tid == 0) {
        volatile unsigned int* f = &g_wflag[t * 4 + ng];
        while (*f == 0u) {}
    }
    __syncthreads();
    __threadfence();
    w_sm[tid >> 4][tid & 15] = __ldcg(&g_w[(n0 + (tid >> 4)) * 16 + (tid & 15)]);
    __syncthreads();

#pragma unroll
    for (int pp = 0; pp < 4; pp++) {
        int p = ks * 4 + pp;
#pragma unroll
        for (int r = 0; r < 16; r++)
            acc[r] += w_sm[r][p] * g_AW[((size_t)(n0 + r) * 16 + p) * H4 + j];
    }
    if (ks) {
#pragma unroll
        for (int r = 0; r < 16; r++) red_sm[ks - 1][r][c] = acc[r];
    }
    __syncthreads();
    float aval[16];
    if (ks == 0) {
#pragma unroll
        for (int r = 0; r < 16; r++) {
            float a = acc[r] + red_sm[0][r][c] + red_sm[1][r][c] + red_sm[2][r][c];
            a += g_xa[((size_t)t * 64 + n0 + r) * H4 + j];
            aval[r] = a;
        }
    }
    __syncthreads();
    if (ks == 0) {
#pragma unroll
        for (int r = 0; r < 16; r++) red_sm[0][r][c] = aval[r];
    }
    __syncthreads();
    {
        int r = tid >> 4, hl = tid & 15;
        float ai = red_sm[0][r][0 * 16 + hl];
        float af = red_sm[0][r][1 * 16 + hl];
        float ao = red_sm[0][r][2 * 16 + hl];
        float ag = red_sm[0][r][3 * 16 + hl];
        float gi = 1.f / (1.f + expf(-ai));
        float gf = 1.f / (1.f + expf(-af));
        float go = 1.f / (1.f + expf(-ao));
        float gg = tanhf(ag);
        int n = n0 + r, hg = hc0 + hl;
        float cp = g_c[n * HH + hg];
        float cn = gf * cp + gi * gg;
        float hn = go * tanhf(cn);
        g_c[n * HH + hg] = cn;
        g_h[wb][n * HH + hg] = hn;
        g_Ah[(size_t)(n * Tt + t) * HH + hg] = __float2half(hn);
    }
}

// ---------------- K_convB: Wv [512][32000] fp32 -> g_BhT [32000][512] fp16 ----------
__global__ void k_convB(const float* __restrict__ Wv) {
    __shared__ float tile[32][33];
    int v0 = blockIdx.x * 32, k0 = blockIdx.y * 32;
    for (int i = threadIdx.y; i < 32; i += 8)
        tile[i][threadIdx.x] = Wv[(size_t)(k0 + i) * VV + v0 + threadIdx.x];
    __syncthreads();
    for (int i = threadIdx.y; i < 32; i += 8)
        g_BhT[(size_t)(v0 + i) * HH + k0 + threadIdx.x] = __float2half(tile[threadIdx.x][i]);
}

// ---------------- K5: fp16 HMMA vocab GEMM (R11-proven) ----------------
#define VBUF 20480
__global__ __launch_bounds__(256)
void k_vocab_mma(const float* __restrict__ bv, float* __restrict__ out) {
    extern __shared__ char smv[];
    uint32_t sb = smem_u32(smv);
    int tid = threadIdx.x;
    int wid = tid >> 5, lane = tid & 31;
    int warp_m = wid & 3;
    int warp_n = wid >> 2;
    int bm = blockIdx.x, bn = blockIdx.y;

    const __half* Ah0 = g_Ah + (size_t)bm * 128 * HH;
    const __half* Bh0 = g_BhT + (size_t)bn * 128 * HH;

    float acc[2][8][4];
#pragma unroll
    for (int a = 0; a < 2; a++)
#pragma unroll
        for (int t = 0; t < 8; t++)
#pragma unroll
            for (int k = 0; k < 4; k++) acc[a][t][k] = 0.f;

    auto issue = [&](int chunk, int b) {
        int k0 = chunk * 32;
        uint32_t base = sb + b * VBUF;
#pragma unroll
        for (int j = 0; j < 2; j++) {
            int idx = tid + j * 256;
            int r = idx >> 2, s = idx & 3;
            uint32_t doff = r * 80 + s * 16;
            size_t goff = (size_t)r * HH + k0 + s * 8;
            cpasync16(base + doff,          Ah0 + goff);
            cpasync16(base + 10240 + doff,  Bh0 + goff);
        }
        cp_commit();
    };

    issue(0, 0);
    for (int i = 0; i < 16; i++) {
        int b = i & 1;
        if (i < 15) issue(i + 1, b ^ 1);
        if (i < 15) asm volatile("cp.async.wait_group 1;" ::: "memory");
        else        asm volatile("cp.async.wait_group 0;" ::: "memory");
        __syncthreads();

        uint32_t abase = sb + b * VBUF;
#pragma unroll
        for (int kc = 0; kc < 2; kc++) {
            uint32_t ah[2][4], bh[4][4];
#pragma unroll
            for (int tm = 0; tm < 2; tm++) {
                int row = warp_m * 32 + tm * 16 + (lane & 15);
                ldmx4(ah[tm], abase + row * 80 + kc * 32 + (lane >> 4) * 16);
            }
#pragma unroll
            for (int g = 0; g < 4; g++) {
                int col = warp_n * 64 + g * 16 + (lane & 15);
                ldmx4(bh[g], abase + 10240 + col * 80 + kc * 32 + (lane >> 4) * 16);
            }
#pragma unroll
            for (int tm = 0; tm < 2; tm++)
#pragma unroll
                for (int tn = 0; tn < 8; tn++) {
                    int g = tn >> 1, p = tn & 1;
                    mma16816h(acc[tm][tn], ah[tm], bh[g][p], bh[g][p + 2]);
                }
        }
        __syncthreads();
    }

#pragma unroll
    for (int tm = 0; tm < 2; tm++) {
        int row = bm * 128 + warp_m * 32 + tm * 16 + (lane >> 2);
#pragma unroll
        for (int tn = 0; tn < 8; tn++) {
            int col = bn * 128 + warp_n * 64 + tn * 8 + (lane & 3) * 2;
            float b0 = bv[col], b1 = bv[col + 1];
            float2 v0 = make_float2(acc[tm][tn][0] + b0, acc[tm][tn][1] + b1);
            float2 v1 = make_float2(acc[tm][tn][2] + b0, acc[tm][tn][3] + b1);
            *(float2*)&out[(size_t)row * VV + col] = v0;
            *(float2*)&out[(size_t)(row + 8) * VV + col] = v1;
        }
    }
}

// ---------------- launcher ----------------
extern "C" void kernel_launch(void* const* d_in, const int* in_sizes, int n_in,
                              void* d_out, int out_size) {
    const float* A      = (const float*)d_in[0];
    const int*   caps   = (const int*)  d_in[1];
    const float* conv_w = (const float*)d_in[2];
    const float* conv_b = (const float*)d_in[3];
    const float* Wx     = (const float*)d_in[4];
    const float* Wh     = (const float*)d_in[5];
    const float* Wattn  = (const float*)d_in[6];
    const float* b      = (const float*)d_in[7];
    const float* We     = (const float*)d_in[8];
    const float* Wv     = (const float*)d_in[9];
    const float* bv     = (const float*)d_in[10];
    float* out = (float*)d_out;

    cudaFuncSetAttribute(k_vocab_mma, cudaFuncAttributeMaxDynamicSharedMemorySize, 2 * VBUF);
    cudaFuncSetAttribute(k_gemm3, cudaFuncAttributeMaxDynamicSharedMemorySize, 2 * VBUF3);

    k_initflags<<<1, 128>>>();
    k_convB<<<dim3(VV / 32, HH / 32), dim3(32, 8)>>>(Wv);
    k_transpose<<<dim3(DA / 32, HH / 32), dim3(32, 8)>>>(conv_w);
    k_convWx<<<dim3(H4 / 32, KXP / 32), dim3(32, 8)>>>(Wx);
    k_convWa<<<dim3(H4 / 32, HH / 32), dim3(32, 8)>>>(Wattn);
    k_gatherX<<<(Tt * Nn * KXP) / 256, 256>>>(caps, We);
    k_conv<<<256, 128>>>(A, conv_b);            // Aproj (+split) + h0/c0
    k_gemm3<<<dim3(16, 16), 256, 2 * VBUF3>>>(0, b, KXP, H4);       // xa
    k_gemm3<<<dim3(8, 16), 256, 2 * VBUF3>>>(1, nullptr, HH, H4);   // AW
    for (int t = 0; t < Tt; t++)
        k_step<<<dim3(33, 4), 256>>>(Wh, t);    // producers + consumers, one launch/step
    k_vocab_mma<<<dim3(16, 250), 256, 2 * VBUF>>>(bv, out);
}